// round 9
// baseline (speedup 1.0000x reference)
#include <cuda_runtime.h>
#include <math.h>

#define B_    128
#define T_    2048
#define NC    8            // concurrent chunks
#define CL    256          // chunk length (T_/NC)
#define K_    20
#define H_    512
#define TILE  32
#define NT    (CL / TILE)  // 8 tiles per chunk
#define TILE_BYTES (TILE * 2 * K_ * 4)     // 5120
#define TILE_V16   (TILE_BYTES / 16)       // 320 x 16B

typedef unsigned long long ull;

// ---------------- device-global scratch ----------------
__device__ float g_ypA[B_ * T_];            // hgroup-0 partial y
__device__ float g_ypB[B_ * T_];            // hgroup-1 partial y
__device__ float g_eM [B_ * 7 * H_];        // local end states per chunk 0..6
__device__ float g_eD1[B_ * 7 * H_];
__device__ float g_eD2[B_ * 7 * H_];
__device__ ull   g_sM [B_ * 7 * 256];       // true start states chunks 1..7, packed pairs
__device__ ull   g_sD1[B_ * 7 * 256];
__device__ ull   g_sD2[B_ * 7 * 256];

// ---------------- packed f32x2 helpers (sm_103a) ----------------
__device__ __forceinline__ ull fma2(ull a, ull b, ull c) {
    ull d; asm("fma.rn.f32x2 %0,%1,%2,%3;" : "=l"(d) : "l"(a), "l"(b), "l"(c)); return d;
}
__device__ __forceinline__ ull add2(ull a, ull b) {
    ull d; asm("add.rn.f32x2 %0,%1,%2;" : "=l"(d) : "l"(a), "l"(b)); return d;
}
__device__ __forceinline__ ull mul2(ull a, ull b) {
    ull d; asm("mul.rn.f32x2 %0,%1,%2;" : "=l"(d) : "l"(a), "l"(b)); return d;
}
__device__ __forceinline__ ull pack2(float lo, float hi) {
    ull d; asm("mov.b64 %0,{%1,%2};" : "=l"(d) : "f"(lo), "f"(hi)); return d;
}
__device__ __forceinline__ float2 asf2(ull v) {
    float2 r; asm("mov.b64 {%0,%1},%2;" : "=f"(r.x), "=f"(r.y) : "l"(v)); return r;
}
__device__ __forceinline__ float sigm(float v) { return 1.0f / (1.0f + expf(-v)); }

// ---------------- cp.async helpers ----------------
__device__ __forceinline__ void cpa16(unsigned s, const void* g) {
    asm volatile("cp.async.cg.shared.global [%0], [%1], 16;" :: "r"(s), "l"(g));
}
__device__ __forceinline__ void cpa_commit() {
    asm volatile("cp.async.commit_group;");
}
template<int N> __device__ __forceinline__ void cpa_wait() {
    asm volatile("cp.async.wait_group %0;" :: "n"(N));
}

// ---------------- kernel 1: fused fold + projection + scan, one chunk, 1 ch/thread ----------------
__global__ void __launch_bounds__(256, 4) scan_kernel(
    const float* __restrict__ x,
    const float* __restrict__ W1, const float* __restrict__ b1,
    const float* __restrict__ W2, const float* __restrict__ b2,
    const float* __restrict__ Wo,
    const float* __restrict__ tm, const float* __restrict__ tn1,
    const float* __restrict__ tn2)
{
    const int bx   = blockIdx.x;                // b(7..4) | c(3..1) | g(0)
    const int b    = bx >> 4;
    const int c    = (bx >> 1) & 7;
    const int g    = bx & 1;
    const int tid  = threadIdx.x;
    const int w    = tid >> 5;
    const int lane = tid & 31;
    const int h    = g * 256 + tid;             // this thread's channel

    // ---- fold parameters for channel h ----
    float al  = sigm(tm[h]);
    float be1 = sigm(tn1[h]);
    float be2 = sigm(tn2[h]);
    float wo  = Wo[h];
    float s1  = wo * (1.0f - al) * (1.0f - be1);
    float s2  = wo * (1.0f - al) * (1.0f - be2);
    ull w1v[K_ / 2], w2v[K_ / 2];
#pragma unroll
    for (int q = 0; q < K_ / 2; q++) {
        w1v[q] = pack2(s1 * W1[h * K_ + 2 * q], s1 * W1[h * K_ + 2 * q + 1]);
        w2v[q] = pack2(s2 * W2[h * K_ + 2 * q], s2 * W2[h * K_ + 2 * q + 1]);
    }
    const ull biasA = pack2(s1 * b1[h], 0.0f);
    const ull biasC = pack2(s2 * b2[h], 0.0f);

    __shared__ __align__(16) float XT[2][TILE][2 * K_];   // raw x, double-buffered
    __shared__ float ypW[2][8][TILE];

    float D1 = 0.0f, D2 = 0.0f, M = 0.0f;

    const float* xb = x + ((size_t)b * T_ + (size_t)c * CL) * (2 * K_);
    float* yp = (g ? g_ypB : g_ypA) + (size_t)b * T_ + (size_t)c * CL;

    const unsigned smemXT0 = (unsigned)__cvta_generic_to_shared(&XT[0][0][0]);
    const unsigned smemXT1 = (unsigned)__cvta_generic_to_shared(&XT[1][0][0]);

    // prologue: stage tile 0 via cp.async
    {
        const char* src = (const char*)xb;
        for (int i = tid; i < TILE_V16; i += 256)
            cpa16(smemXT0 + i * 16, src + i * 16);
        cpa_commit();
        cpa_wait<0>();
    }
    __syncthreads();

    int cur = 0;
#pragma unroll 1
    for (int tile = 0; tile < NT; tile++) {
        // stage next tile into the other buffer (async, overlapped with compute)
        if (tile + 1 < NT) {
            const char* src = (const char*)(xb + (size_t)(tile + 1) * (TILE * 2 * K_));
            const unsigned dst = cur ? smemXT0 : smemXT1;
            for (int i = tid; i < TILE_V16; i += 256)
                cpa16(dst + i * 16, src + i * 16);
        }
        cpa_commit();

#pragma unroll 2
        for (int tq = 0; tq < TILE / 4; tq++) {
            float p[4];
#pragma unroll
            for (int u = 0; u < 4; u++) {
                const int tt = tq * 4 + u;
                ull Aa = biasA, Ab = 0ull, Ca = biasC, Cb = 0ull;
#pragma unroll
                for (int q = 0; q < 5; q++) {
                    ulonglong2 v = *reinterpret_cast<const ulonglong2*>(&XT[cur][tt][4 * q]);
                    Aa = fma2(w1v[2 * q],     v.x, Aa);
                    Ab = fma2(w1v[2 * q + 1], v.y, Ab);
                }
#pragma unroll
                for (int q = 0; q < 5; q++) {
                    ulonglong2 v = *reinterpret_cast<const ulonglong2*>(&XT[cur][tt][K_ + 4 * q]);
                    Ca = fma2(w2v[2 * q],     v.x, Ca);
                    Cb = fma2(w2v[2 * q + 1], v.y, Cb);
                }
                float2 f1 = asf2(add2(Aa, Ab));
                float2 f2 = asf2(add2(Ca, Cb));
                D1 = fmaf(be1, D1, f1.x + f1.y);
                D2 = fmaf(be2, D2, f2.x + f2.y);
                M  = fmaf(al,  M,  D1 + D2);
                p[u] = M;
            }
#pragma unroll
            for (int off = 16; off > 0; off >>= 1) {
#pragma unroll
                for (int u = 0; u < 4; u++)
                    p[u] += __shfl_down_sync(0xffffffffu, p[u], off);
            }
            if (lane == 0)
                *reinterpret_cast<float4*>(&ypW[cur][w][tq * 4]) =
                    make_float4(p[0], p[1], p[2], p[3]);
        }

        cpa_wait<1>();
        __syncthreads();

        // balanced drain: each warp handles 4 timesteps of this tile
        if (lane < 4) {
            const int t = w * 4 + lane;
            float s = 0.0f;
#pragma unroll
            for (int w8 = 0; w8 < 8; w8++) s += ypW[cur][w8][t];
            yp[tile * TILE + t] = s;
        }
        cur ^= 1;
    }

    if (c < 7) {
        const size_t si = ((size_t)b * 7 + c) * H_ + h;
        g_eM [si] = M;
        g_eD1[si] = D1;
        g_eD2[si] = D2;
    }
}

// stable S = (a^{d+1} - bb^{d+1})/(a - bb) given Ax=a^{d+1}, Bx=bb^{d+1}
__device__ __forceinline__ float seedS(float a, float bb, int d, float Ax, float Bx) {
    float diff = a - bb;
    if (fabsf(diff) > 0.04f * a) return (Ax - Bx) / diff;
    float lr  = log1pf((bb - a) / a);
    float den = -expm1f(lr);
    float ad  = Ax / a;
    if (den == 0.0f) return (float)(d + 1) * ad;
    float num = -expm1f((float)(d + 1) * lr);
    return ad * (num / den);
}

// ---------------- kernel 2: propagate true start states across chunks ----------------
__global__ void __launch_bounds__(256) combine_kernel(
    const float* __restrict__ tm, const float* __restrict__ tn1,
    const float* __restrict__ tn2)
{
    const int b = blockIdx.x;      // 128
    const int p = threadIdx.x;     // pair index: channels 2p, 2p+1

    float sM[2]  = {0.f, 0.f}, sD1[2] = {0.f, 0.f}, sD2[2] = {0.f, 0.f};
    float aL[2], b1L[2], b2L[2], G1L[2], G2L[2];
#pragma unroll
    for (int hh = 0; hh < 2; hh++) {
        const int h = 2 * p + hh;
        float al  = sigm(tm[h]);
        float be1 = sigm(tn1[h]);
        float be2 = sigm(tn2[h]);
        float la = log2f(al), l1 = log2f(be1), l2 = log2f(be2);
        aL[hh]  = exp2f(256.0f * la);
        b1L[hh] = exp2f(256.0f * l1);
        b2L[hh] = exp2f(256.0f * l2);
        G1L[hh] = be1 * seedS(al, be1, 255, aL[hh], b1L[hh]);
        G2L[hh] = be2 * seedS(al, be2, 255, aL[hh], b2L[hh]);
    }

#pragma unroll
    for (int c = 0; c < 7; c++) {
        const size_t ei = ((size_t)b * 7 + c) * H_ + 2 * p;
#pragma unroll
        for (int hh = 0; hh < 2; hh++) {
            float eM  = g_eM [ei + hh];
            float eD1 = g_eD1[ei + hh];
            float eD2 = g_eD2[ei + hh];
            float nM  = aL[hh] * sM[hh] + G1L[hh] * sD1[hh] + G2L[hh] * sD2[hh] + eM;
            float nD1 = b1L[hh] * sD1[hh] + eD1;
            float nD2 = b2L[hh] * sD2[hh] + eD2;
            sM[hh] = nM; sD1[hh] = nD1; sD2[hh] = nD2;
        }
        const size_t si = ((size_t)b * 7 + c) * 256 + p;
        g_sM [si] = pack2(sM[0],  sM[1]);
        g_sD1[si] = pack2(sD1[0], sD1[1]);
        g_sD2[si] = pack2(sD2[0], sD2[1]);
    }
}

// ---------------- kernel 3: correction + sigmoid (c==0 handles chunk 0 plain) ----------------
__global__ void __launch_bounds__(256) corr_kernel(
    float* __restrict__ out, const float* __restrict__ bo,
    const float* __restrict__ tm, const float* __restrict__ tn1,
    const float* __restrict__ tn2)
{
    const int b    = blockIdx.x >> 3;
    const int c    = blockIdx.x & 7;           // chunk index
    const int tid  = threadIdx.x;

    if (c == 0) {
        // chunk 0: no correction needed
        const size_t idx = (size_t)b * T_ + tid;
        out[idx] = 1.0f / (1.0f + expf(-(g_ypA[idx] + g_ypB[idx] + bo[0])));
        return;
    }

    const int w    = tid >> 5;
    const int lane = tid & 31;
    const int p    = tid;                      // pair: channels 2p, 2p+1

    // coefficient seeds at delta=0: A=alpha, P=beta, G=beta (exactly)
    float al0  = sigm(tm[2 * p]),  al1  = sigm(tm[2 * p + 1]);
    float be10 = sigm(tn1[2 * p]), be11 = sigm(tn1[2 * p + 1]);
    float be20 = sigm(tn2[2 * p]), be21 = sigm(tn2[2 * p + 1]);
    ull alp = pack2(al0, al1);
    ull b1p = pack2(be10, be11);
    ull b2p = pack2(be20, be21);
    ull A  = alp, P1 = b1p, G1 = b1p, P2 = b2p, G2 = b2p;

    const size_t si = ((size_t)b * 7 + (c - 1)) * 256 + p;
    const ull M0  = g_sM [si];
    const ull D10 = g_sD1[si];
    const ull D20 = g_sD2[si];

    __shared__ float part[8][CL];

#pragma unroll 1
    for (int d = 0; d < CL; d++) {
        ull acc = fma2(A, M0, fma2(G1, D10, mul2(G2, D20)));
        A  = mul2(alp, A);
        P1 = mul2(b1p, P1);
        G1 = fma2(alp, G1, P1);
        P2 = mul2(b2p, P2);
        G2 = fma2(alp, G2, P2);
        float2 f = asf2(acc);
        float s = f.x + f.y;
#pragma unroll
        for (int off = 16; off > 0; off >>= 1)
            s += __shfl_down_sync(0xffffffffu, s, off);
        if (lane == 0) part[w][d] = s;
    }
    __syncthreads();

    // combine 8 warp partials + base y + bias, sigmoid
    {
        const int t = c * CL + tid;
        float s = bo[0];
#pragma unroll
        for (int w8 = 0; w8 < 8; w8++) s += part[w8][tid];
        s += g_ypA[(size_t)b * T_ + t] + g_ypB[(size_t)b * T_ + t];
        out[(size_t)b * T_ + t] = 1.0f / (1.0f + expf(-s));
    }
}

// ---------------- launch ----------------
extern "C" void kernel_launch(void* const* d_in, const int* in_sizes, int n_in,
                              void* d_out, int out_size) {
    const float* x   = (const float*)d_in[0];
    const float* W1  = (const float*)d_in[1];
    const float* b1  = (const float*)d_in[2];
    const float* W2  = (const float*)d_in[3];
    const float* b2  = (const float*)d_in[4];
    const float* Wo  = (const float*)d_in[5];
    const float* bo  = (const float*)d_in[6];
    const float* tm  = (const float*)d_in[7];
    const float* tn1 = (const float*)d_in[8];
    const float* tn2 = (const float*)d_in[9];
    float* out = (float*)d_out;

    scan_kernel<<<B_ * NC * 2, 256>>>(x, W1, b1, W2, b2, Wo, tm, tn1, tn2);
    combine_kernel<<<B_, 256>>>(tm, tn1, tn2);
    corr_kernel<<<B_ * NC, 256>>>(out, bo, tm, tn1, tn2);
}